// round 10
// baseline (speedup 1.0000x reference)
#include <cuda_runtime.h>

#define D     1024
#define HD    4096
#define LNUM  12
#define VOCAB 50257
#define NT    512
#define NW    16

// ---------------- global scratch ----------------
__device__ float g_x[D];
__device__ float g_k[D];
__device__ float g_v[D];
__device__ float g_r[D];
__device__ float g_k2[HD];
__device__ float g_r2[D];
__device__ float g_accD[D];

// ---------------- barrier state ----------------
__device__ unsigned g_bar_gen = 0;
__device__ unsigned g_leaf[8 * 128];
__device__ unsigned g_root = 0;

// ---------------- cp.async / prefetch helpers ----------------
__device__ __forceinline__ void cp16s(float* s, const float4* g) {
    unsigned sa = (unsigned)__cvta_generic_to_shared(s);
    asm volatile("cp.async.ca.shared.global [%0], [%1], 16;" :: "r"(sa), "l"(g));
}
__device__ __forceinline__ void cp_commit_g() {
    asm volatile("cp.async.commit_group;" ::: "memory");
}
__device__ __forceinline__ void cp_wait_all_g() {
    asm volatile("cp.async.wait_all;" ::: "memory");
}
__device__ __forceinline__ void l2pf(const float* p) {
    asm volatile("prefetch.global.L2 [%0];" :: "l"(p));
}

// stage up to 5 rows of 1024 floats into stg (cp.async, threads 0..255)
__device__ __forceinline__ void stage5(float* stg, int tid,
        const float* p0, const float* p1, const float* p2,
        const float* p3, const float* p4) {
    if (tid < 256) {
        if (p0) cp16s(stg +        tid * 4, (const float4*)p0 + tid);
        if (p1) cp16s(stg + 1024 + tid * 4, (const float4*)p1 + tid);
        if (p2) cp16s(stg + 2048 + tid * 4, (const float4*)p2 + tid);
        if (p3) cp16s(stg + 3072 + tid * 4, (const float4*)p3 + tid);
        if (p4) cp16s(stg + 4096 + tid * 4, (const float4*)p4 + tid);
        cp_commit_g();
    }
}

// ---------------- split grid barrier ----------------
__device__ __forceinline__ void gb_arrive(int nb, volatile unsigned* s_gen) {
    __threadfence();
    __syncthreads();
    if (threadIdx.x == 0) {
        *s_gen = *((volatile unsigned*)&g_bar_gen);
        int leaf = blockIdx.x & 7;
        unsigned target = (unsigned)((nb >> 3) + ((blockIdx.x & 7) < (nb & 7) ? 1 : 0));
        if (atomicAdd(&g_leaf[leaf * 128], 1u) == target - 1u) {
            g_leaf[leaf * 128] = 0;
            __threadfence();
            if (atomicAdd(&g_root, 1u) == 7u) {
                g_root = 0;
                __threadfence();
                atomicAdd(&g_bar_gen, 1u);
            }
        }
    }
}
__device__ __forceinline__ void gb_wait(volatile unsigned* s_gen) {
    if (threadIdx.x == 0) {
        unsigned gen = *s_gen;
        while (*((volatile unsigned*)&g_bar_gen) == gen) { }
        __threadfence();
    }
    __syncthreads();
}

// ---------------- block-wide sum ----------------
__device__ __forceinline__ float block_sum(float v, float* sred) {
    int lane = threadIdx.x & 31, wid = threadIdx.x >> 5;
    #pragma unroll
    for (int o = 16; o; o >>= 1) v += __shfl_xor_sync(0xffffffffu, v, o);
    if (lane == 0) sred[wid] = v;
    __syncthreads();
    float t = 0.f;
    if (wid == 0) {
        t = (lane < NW) ? sred[lane] : 0.f;
        #pragma unroll
        for (int o = 8; o; o >>= 1) t += __shfl_xor_sync(0xffffffffu, t, o);
        if (lane == 0) sred[0] = t;
    }
    __syncthreads();
    float r = sred[0];
    __syncthreads();
    return r;
}

// ---------------- item machinery ----------------
__device__ __forceinline__ void preload8(float4* P, const float* w, int lane) {
    const float4* w4 = (const float4*)w;
    #pragma unroll
    for (int u = 0; u < 8; u++) P[u] = __ldg(w4 + u * 32 + lane);
}

// Items of 1024 floats; P holds the preloaded first item (index gw).
template<class RowP, class VecP, class Fin>
__device__ __forceinline__ void run_items(int NR, int gw, int nwG, int lane,
                                          const float4* P, RowP rowp, VecP vecp, Fin fin) {
    float4 A[8];
    #pragma unroll
    for (int u = 0; u < 8; u++) A[u] = P[u];
    for (int t = gw; t < NR; t += nwG) {
        float4 B[8];
        int nx = t + nwG;
        if (nx < NR) {
            const float4* w4 = (const float4*)rowp(nx);
            #pragma unroll
            for (int u = 0; u < 8; u++) B[u] = __ldg(w4 + u * 32 + lane);
        }
        const float4* v4 = (const float4*)vecp(t);
        float s0 = 0.f, s1 = 0.f, s2 = 0.f, s3 = 0.f;
        #pragma unroll
        for (int u = 0; u < 8; u++) {
            float4 b = v4[u * 32 + lane];
            s0 = fmaf(A[u].x, b.x, s0); s1 = fmaf(A[u].y, b.y, s1);
            s2 = fmaf(A[u].z, b.z, s2); s3 = fmaf(A[u].w, b.w, s3);
        }
        float r = (s0 + s1) + (s2 + s3);
        #pragma unroll
        for (int o = 16; o; o >>= 1) r += __shfl_xor_sync(0xffffffffu, r, o);
        fin(t, r);
        #pragma unroll
        for (int u = 0; u < 8; u++) A[u] = B[u];
    }
}

__global__ __launch_bounds__(NT, 1) void rwkv_persistent(
    const int*   __restrict__ ctx,
    const float* __restrict__ st_in,
    const float* __restrict__ emb,
    const float* __restrict__ ln0,
    const float* __restrict__ ln1,
    const float* __restrict__ ln2,
    const float* __restrict__ lnout,
    const float* __restrict__ tmk,
    const float* __restrict__ tmv,
    const float* __restrict__ tmr,
    const float* __restrict__ tfirst,
    const float* __restrict__ tdecay,
    const float* __restrict__ kw,
    const float* __restrict__ vw,
    const float* __restrict__ rw,
    const float* __restrict__ ow,
    const float* __restrict__ ftmk,
    const float* __restrict__ ftmr,
    const float* __restrict__ fkw,
    const float* __restrict__ fvw,
    const float* __restrict__ frw,
    const float* __restrict__ head,
    float* __restrict__ out,
    int nb)
{
    __shared__ float vecS[3 * D];
    __shared__ float xpark[D];
    __shared__ float stg[5 * 1024];
    __shared__ float sred[NW];
    __shared__ unsigned s_gen;

    const int tid  = threadIdx.x;
    const int lane = tid & 31;
    const int bid  = blockIdx.x;
    const int gw   = bid * NW + (tid >> 5);
    const int nwG  = nb * NW;

    float* out_logits = out;
    float* out_state  = out + VOCAB;

    float4 P[8];

    // ---------- prologue ----------
    stage5(stg, tid, ln1, tmk, tmv, tmr, st_in + D);
    if (gw < 3 * D) {
        int m = gw >> 10, r = gw & 1023;
        const float* base = (m == 0) ? kw : ((m == 1) ? vw : rw);
        preload8(P, base + (size_t)r * D, lane);
        if (gw + nwG < 3 * D) {
            int m2 = (gw + nwG) >> 10, r2 = (gw + nwG) & 1023;
            const float* b2 = (m2 == 0) ? kw : ((m2 == 1) ? vw : rw);
            l2pf(b2 + (size_t)r2 * D + lane * 32);
        }
    }
    if (bid == 0) {
        const float* e = emb + (size_t)ctx[0] * D;
        float ss = 0.f;
        for (int j = tid; j < D; j += NT) { float t = e[j]; ss += t * t; }
        ss = block_sum(ss, sred);
        float inv = rsqrtf(ss * (1.f / D) + 1e-5f);
        for (int j = tid; j < D; j += NT) g_x[j] = e[j] * inv * ln0[j];
    }
    gb_arrive(nb, &s_gen);
    cp_wait_all_g();
    gb_wait(&s_gen);

    for (int l = 0; l < LNUM; l++) {
        const float* st_l  = st_in     + (size_t)l * 5 * D;
        float*       ost_l = out_state + (size_t)l * 5 * D;
        const float* kwl  = kw  + (size_t)l * D * D;
        const float* vwl  = vw  + (size_t)l * D * D;
        const float* rwl  = rw  + (size_t)l * D * D;
        const float* owl  = ow  + (size_t)l * D * D;
        const float* fkwl = fkw + (size_t)l * HD * D;
        const float* frwl = frw + (size_t)l * D * D;
        const float* fvwl = fvw + (size_t)l * D * HD;
        const float scp = (l > 0 && (l % 6 == 0)) ? 0.5f : 1.0f;

        // ===== stage A: fold prev tail, rms, token-mix; k/v/r matvecs =====
        {
            float ss = 0.f;
            for (int j = tid; j < D; j += NT) {
                float xv = g_x[j];
                if (l > 0) {
                    float sr = 1.f / (1.f + __expf(-g_r2[j]));
                    xv = (xv + sr * g_accD[j]) * scp;
                }
                xpark[j] = xv;
                ss += xv * xv;
            }
            ss = block_sum(ss, sred);
            float inv = rsqrtf(ss * (1.f / D) + 1e-5f);
            for (int j = tid; j < D; j += NT) {
                float xv  = xpark[j];
                float xxj = xv * inv * stg[j];
                float sa  = stg[4096 + j];
                if (bid == 0) { ost_l[D + j] = xxj; if (l > 0) g_x[j] = xv; }
                float a_ = stg[1024 + j]; vecS[j]         = xxj * a_ + sa * (1.f - a_);
                float b_ = stg[2048 + j]; vecS[D + j]     = xxj * b_ + sa * (1.f - b_);
                float c_ = stg[3072 + j]; vecS[2 * D + j] = xxj * c_ + sa * (1.f - c_);
            }
            __syncthreads();
            run_items(3 * D, gw, nwG, lane, P,
                [&](int t) {
                    int m = t >> 10, r = t & 1023;
                    const float* base = (m == 0) ? kwl : ((m == 1) ? vwl : rwl);
                    return base + (size_t)r * D;
                },
                [&](int t) { return (const float*)(vecS + (t >> 10) * 1024); },
                [&](int t, float r) {
                    if (lane == 0) {
                        int m = t >> 10, rr = t & 1023;
                        if (m == 0)      g_k[rr] = r;
                        else if (m == 1) g_v[rr] = r;
                        else             g_r[rr] = r;
                    }
                });
        }
        gb_arrive(nb, &s_gen);
        stage5(stg, tid, tfirst + l * D, tdecay + l * D,
               st_l + 2 * D, st_l + 3 * D, st_l + 4 * D);
        if (gw < D) preload8(P, owl + (size_t)gw * D, lane);
        cp_wait_all_g();
        gb_wait(&s_gen);

        // ===== stage B: WKV prep; ow matvec =====
        {
            for (int j = tid; j < D; j += NT) {
                float k  = g_k[j], v = g_v[j], rr = g_r[j];
                float aa = stg[2048 + j], bb = stg[3072 + j], pp = stg[4096 + j];
                float ww = stg[j] + k;
                float p  = fmaxf(pp, ww);
                float e1 = __expf(pp - p), e2 = __expf(ww - p);
                float a  = e1 * aa + e2 * v;
                float b  = e1 * bb + e2;
                float sr = 1.f / (1.f + __expf(-rr));
                vecS[j] = sr * (a / b);
                if (bid == 0) {
                    float ww2 = pp + stg[1024 + j];
                    float p2  = fmaxf(ww2, k);
                    float e1b = __expf(ww2 - p2), e2b = __expf(k - p2);
                    ost_l[2 * D + j] = e1b * aa + e2b * v;
                    ost_l[3 * D + j] = e1b * bb + e2b;
                    ost_l[4 * D + j] = p2;
                }
            }
            __syncthreads();
            run_items(D, gw, nwG, lane, P,
                [&](int t) { return owl + (size_t)t * D; },
                [&](int t) { (void)t; return (const float*)vecS; },
                [&](int t, float r) { if (lane == 0) g_x[t] += r; });
        }
        gb_arrive(nb, &s_gen);
        stage5(stg, tid, ln2 + l * D, ftmk + l * D, ftmr + l * D, st_l, 0);
        if (gw < HD + D) {
            const float* w0 = (gw < HD) ? fkwl + (size_t)gw * D
                                        : frwl + (size_t)(gw - HD) * D;
            preload8(P, w0, lane);
            int g2 = gw + nwG;
            if (g2 < HD + D) {
                const float* w1 = (g2 < HD) ? fkwl + (size_t)g2 * D
                                            : frwl + (size_t)(g2 - HD) * D;
                l2pf(w1 + lane * 32);
            }
        }
        cp_wait_all_g();
        gb_wait(&s_gen);

        // ===== stage C: rms2, channel-mix prep; fkw/frw =====
        {
            float ss = 0.f;
            for (int j = tid; j < D; j += NT) { float t = g_x[j]; ss += t * t; }
            ss = block_sum(ss, sred);
            float inv = rsqrtf(ss * (1.f / D) + 1e-5f);
            for (int j = tid; j < D; j += NT) {
                float yyj = g_x[j] * inv * stg[j];
                float ff  = stg[3072 + j];
                float a_ = stg[1024 + j]; vecS[j]     = yyj * a_ + ff * (1.f - a_);
                float b_ = stg[2048 + j]; vecS[D + j] = yyj * b_ + ff * (1.f - b_);
                if (bid == 0) ost_l[j] = yyj;
            }
            if (bid < 2) g_accD[bid * 512 + tid] = 0.f;
            __syncthreads();
            run_items(HD + D, gw, nwG, lane, P,
                [&](int t) {
                    return (t < HD) ? fkwl + (size_t)t * D
                                    : frwl + (size_t)(t - HD) * D;
                },
                [&](int t) { return (const float*)((t < HD) ? vecS : vecS + D); },
                [&](int t, float r) {
                    if (lane == 0) {
                        if (t < HD) { r = fmaxf(r, 0.f); g_k2[t] = r * r; }
                        else        g_r2[t - HD] = r;
                    }
                });
        }
        gb_arrive(nb, &s_gen);
        if (gw < 4 * D) {
            preload8(P, fvwl + (size_t)(gw >> 2) * HD + (gw & 3) * 1024, lane);
            int g2 = gw + nwG;
            if (g2 < 4 * D)
                l2pf(fvwl + (size_t)(g2 >> 2) * HD + (g2 & 3) * 1024 + lane * 32);
        }
        gb_wait(&s_gen);

        // ===== stage D: fvw 1K-float chunks into accD =====
        {
            stage5(stg, tid, g_k2, g_k2 + 1024, g_k2 + 2048, g_k2 + 3072, 0);
            cp_wait_all_g();
            __syncthreads();
            run_items(4 * D, gw, nwG, lane, P,
                [&](int t) { return fvwl + (size_t)(t >> 2) * HD + (t & 3) * 1024; },
                [&](int t) { return (const float*)(stg + (t & 3) * 1024); },
                [&](int t, float r) { if (lane == 0) atomicAdd(&g_accD[t >> 2], r); });
        }
        gb_arrive(nb, &s_gen);
        if (l < LNUM - 1) {
            stage5(stg, tid, ln1 + (l + 1) * D, tmk + (l + 1) * D,
                   tmv + (l + 1) * D, tmr + (l + 1) * D,
                   st_in + (size_t)(l + 1) * 5 * D + D);
            if (gw < 3 * D) {
                int m = gw >> 10, r = gw & 1023;
                const float* base = (m == 0) ? kw : ((m == 1) ? vw : rw);
                preload8(P, base + (size_t)(l + 1) * D * D + (size_t)r * D, lane);
                if (gw + nwG < 3 * D) {
                    int m2 = (gw + nwG) >> 10, r2 = (gw + nwG) & 1023;
                    const float* b2 = (m2 == 0) ? kw : ((m2 == 1) ? vw : rw);
                    l2pf(b2 + (size_t)(l + 1) * D * D + (size_t)r2 * D + lane * 32);
                }
            }
        } else {
            stage5(stg, tid, lnout, 0, 0, 0, 0);
            preload8(P, head + (size_t)gw * D, lane);
            if (gw + nwG < VOCAB) l2pf(head + (size_t)(gw + nwG) * D + lane * 32);
        }
        cp_wait_all_g();
        gb_wait(&s_gen);
    }

    // ===== head =====
    {
        const float scp = (LNUM % 6 == 0) ? 0.5f : 1.0f;
        float ss = 0.f;
        for (int j = tid; j < D; j += NT) {
            float sr = 1.f / (1.f + __expf(-g_r2[j]));
            float xv = (g_x[j] + sr * g_accD[j]) * scp;
            xpark[j] = xv;
            ss += xv * xv;
        }
        ss = block_sum(ss, sred);
        float inv = rsqrtf(ss * (1.f / D) + 1e-5f);
        for (int j = tid; j < D; j += NT) vecS[j] = xpark[j] * inv * stg[j];
        __syncthreads();
        run_items(VOCAB, gw, nwG, lane, P,
            [&](int t) { return head + (size_t)t * D; },
            [&](int t) { (void)t; return (const float*)vecS; },
            [&](int t, float r) { if (lane == 0) out_logits[t] = r; });
    }
}

extern "C" void kernel_launch(void* const* d_in, const int* in_sizes, int n_in,
                              void* d_out, int out_size) {
    (void)in_sizes; (void)n_in; (void)out_size;
    int nb = 0;
    cudaDeviceGetAttribute(&nb, cudaDevAttrMultiProcessorCount, 0);
    if (nb <= 0) nb = 148;
    if (nb > 1024) nb = 1024;

    rwkv_persistent<<<nb, NT>>>(
        (const int*)  d_in[0],   // ctx
        (const float*)d_in[1],   // state
        (const float*)d_in[2],   // emb
        (const float*)d_in[3],   // ln0_w
        (const float*)d_in[4],   // ln1_w
        (const float*)d_in[5],   // ln2_w
        (const float*)d_in[6],   // lnout_w
        (const float*)d_in[7],   // att_tmk
        (const float*)d_in[8],   // att_tmv
        (const float*)d_in[9],   // att_tmr
        (const float*)d_in[10],  // att_tfirst
        (const float*)d_in[11],  // att_tdecay
        (const float*)d_in[12],  // att_kw
        (const float*)d_in[13],  // att_vw
        (const float*)d_in[14],  // att_rw
        (const float*)d_in[15],  // att_ow
        (const float*)d_in[16],  // ffn_tmk
        (const float*)d_in[17],  // ffn_tmr
        (const float*)d_in[18],  // ffn_kw
        (const float*)d_in[19],  // ffn_vw
        (const float*)d_in[20],  // ffn_rw
        (const float*)d_in[21],  // head
        (float*)d_out, nb);
}

// round 11
// speedup vs baseline: 1.2576x; 1.2576x over previous
#include <cuda_runtime.h>

#define D     1024
#define HD    4096
#define LNUM  12
#define VOCAB 50257
#define NT    512
#define NW    16

// ---------------- global scratch ----------------
__device__ float g_x[2][D];        // ping-pong residual stream
__device__ float g_k[D];
__device__ float g_v[D];
__device__ float g_r[D];
__device__ float g_k2[HD];
__device__ float g_r2[D];
__device__ float g_accD[D];        // fvw partials

// ---------------- 2-level software grid barrier ----------------
__device__ unsigned g_bar_gen = 0;
__device__ unsigned g_leaf[8 * 128];
__device__ unsigned g_root = 0;

__device__ __forceinline__ void grid_barrier(int nb) {
    __syncthreads();
    if (threadIdx.x == 0) {
        __threadfence();
        unsigned gen = *((volatile unsigned*)&g_bar_gen);
        int leaf = blockIdx.x & 7;
        unsigned target = (unsigned)((nb >> 3) + ((blockIdx.x & 7) < (nb & 7) ? 1 : 0));
        if (atomicAdd(&g_leaf[leaf * 128], 1u) == target - 1u) {
            g_leaf[leaf * 128] = 0;
            __threadfence();
            if (atomicAdd(&g_root, 1u) == 7u) {
                g_root = 0;
                __threadfence();
                atomicAdd(&g_bar_gen, 1u);
            }
        }
        while (*((volatile unsigned*)&g_bar_gen) == gen) { }
        __threadfence();
    }
    __syncthreads();
}

// ---------------- block-wide sum ----------------
__device__ __forceinline__ float block_sum(float v, float* sred) {
    int lane = threadIdx.x & 31, wid = threadIdx.x >> 5;
    #pragma unroll
    for (int o = 16; o; o >>= 1) v += __shfl_xor_sync(0xffffffffu, v, o);
    if (lane == 0) sred[wid] = v;
    __syncthreads();
    float t = 0.f;
    if (wid == 0) {
        t = (lane < NW) ? sred[lane] : 0.f;
        #pragma unroll
        for (int o = 8; o; o >>= 1) t += __shfl_xor_sync(0xffffffffu, t, o);
        if (lane == 0) sred[0] = t;
    }
    __syncthreads();
    float r = sred[0];
    __syncthreads();
    return r;
}

// ---------------- single-item dot: 1024 floats, 8 batched LDG.128 ----------------
__device__ __forceinline__ float dot1k(const float* __restrict__ w,
                                       const float* __restrict__ vec, int lane) {
    const float4* __restrict__ w4 = reinterpret_cast<const float4*>(w);
    const float4* __restrict__ v4 = reinterpret_cast<const float4*>(vec);
    float4 a[8];
    #pragma unroll
    for (int u = 0; u < 8; u++) a[u] = __ldg(w4 + u * 32 + lane);
    float s0 = 0.f, s1 = 0.f, s2 = 0.f, s3 = 0.f;
    #pragma unroll
    for (int u = 0; u < 8; u++) {
        float4 b = v4[u * 32 + lane];
        s0 = fmaf(a[u].x, b.x, s0); s1 = fmaf(a[u].y, b.y, s1);
        s2 = fmaf(a[u].z, b.z, s2); s3 = fmaf(a[u].w, b.w, s3);
    }
    float t = (s0 + s1) + (s2 + s3);
    #pragma unroll
    for (int o = 16; o; o >>= 1) t += __shfl_xor_sync(0xffffffffu, t, o);
    return t;
}

// ---------------- dual-item loop: two 1024-float items' loads in flight ----------------
template<class RowP, class VecP, class Fin>
__device__ __forceinline__ void dual_items(int NR, int gw, int nwG, int lane,
                                           RowP rowp, VecP vecp, Fin fin) {
    for (int t = gw; t < NR; t += 2 * nwG) {
        int t2 = t + nwG;
        bool has2 = t2 < NR;
        const float4* w0 = (const float4*)rowp(t);
        float4 a0[8];
        #pragma unroll
        for (int u = 0; u < 8; u++) a0[u] = __ldg(w0 + u * 32 + lane);
        float4 a1[8];
        if (has2) {
            const float4* w1 = (const float4*)rowp(t2);
            #pragma unroll
            for (int u = 0; u < 8; u++) a1[u] = __ldg(w1 + u * 32 + lane);
        }
        {
            const float4* v0 = (const float4*)vecp(t);
            float s0 = 0.f, s1 = 0.f, s2 = 0.f, s3 = 0.f;
            #pragma unroll
            for (int u = 0; u < 8; u++) {
                float4 b = v0[u * 32 + lane];
                s0 = fmaf(a0[u].x, b.x, s0); s1 = fmaf(a0[u].y, b.y, s1);
                s2 = fmaf(a0[u].z, b.z, s2); s3 = fmaf(a0[u].w, b.w, s3);
            }
            float r = (s0 + s1) + (s2 + s3);
            #pragma unroll
            for (int o = 16; o; o >>= 1) r += __shfl_xor_sync(0xffffffffu, r, o);
            fin(t, r);
        }
        if (has2) {
            const float4* v1 = (const float4*)vecp(t2);
            float s0 = 0.f, s1 = 0.f, s2 = 0.f, s3 = 0.f;
            #pragma unroll
            for (int u = 0; u < 8; u++) {
                float4 b = v1[u * 32 + lane];
                s0 = fmaf(a1[u].x, b.x, s0); s1 = fmaf(a1[u].y, b.y, s1);
                s2 = fmaf(a1[u].z, b.z, s2); s3 = fmaf(a1[u].w, b.w, s3);
            }
            float r = (s0 + s1) + (s2 + s3);
            #pragma unroll
            for (int o = 16; o; o >>= 1) r += __shfl_xor_sync(0xffffffffu, r, o);
            fin(t2, r);
        }
    }
}

__global__ __launch_bounds__(NT, 1) void rwkv_persistent(
    const int*   __restrict__ ctx,
    const float* __restrict__ st_in,
    const float* __restrict__ emb,
    const float* __restrict__ ln0,
    const float* __restrict__ ln1,
    const float* __restrict__ ln2,
    const float* __restrict__ lnout,
    const float* __restrict__ tmk,
    const float* __restrict__ tmv,
    const float* __restrict__ tmr,
    const float* __restrict__ tfirst,
    const float* __restrict__ tdecay,
    const float* __restrict__ kw,
    const float* __restrict__ vw,
    const float* __restrict__ rw,
    const float* __restrict__ ow,
    const float* __restrict__ ftmk,
    const float* __restrict__ ftmr,
    const float* __restrict__ fkw,
    const float* __restrict__ fvw,
    const float* __restrict__ frw,
    const float* __restrict__ head,
    float* __restrict__ out,
    int nb)
{
    __shared__ float sbuf[4096];   // 16 KB: stage vecs / xpark / k2 copy
    __shared__ float sred[NW];

    const int tid  = threadIdx.x;
    const int lane = tid & 31;
    const int bid  = blockIdx.x;
    const int gw   = bid * NW + (tid >> 5);
    const int nwG  = nb * NW;

    float* out_logits = out;
    float* out_state  = out + VOCAB;

    // ---------- stage 0: x = rms(emb[ctx[0]], ln0) into g_x[0] ----------
    if (bid == 0) {
        const float* e = emb + (size_t)ctx[0] * D;
        float ss = 0.f;
        for (int j = tid; j < D; j += NT) { float t = e[j]; ss += t * t; }
        ss = block_sum(ss, sred);
        float inv = rsqrtf(ss * (1.f / D) + 1e-5f);
        for (int j = tid; j < D; j += NT) g_x[0][j] = e[j] * inv * ln0[j];
    }
    grid_barrier(nb);

    for (int l = 0; l < LNUM; l++) {
        const int p = l & 1, np = p ^ 1;
        const float scp = (l > 0 && (l % 6 == 0)) ? 0.5f : 1.0f;  // prev layer's rescale
        const float* st_l  = st_in     + (size_t)l * 5 * D;
        float*       ost_l = out_state + (size_t)l * 5 * D;
        const float* kwl  = kw  + (size_t)l * D * D;
        const float* vwl  = vw  + (size_t)l * D * D;
        const float* rwl  = rw  + (size_t)l * D * D;
        const float* owl  = ow  + (size_t)l * D * D;
        const float* fkwl = fkw + (size_t)l * HD * D;
        const float* frwl = frw + (size_t)l * D * D;
        const float* fvwl = fvw + (size_t)l * D * HD;

        // ---------- stage A: fold prev tail + rms + token-mix; k/v/r ----------
        {
            float ss = 0.f;
            for (int j = tid; j < D; j += NT) {
                float xv = g_x[p][j];
                if (l > 0) {
                    float sr = 1.f / (1.f + __expf(-g_r2[j]));
                    xv = (xv + sr * g_accD[j]) * scp;
                }
                sbuf[3 * D + j] = xv;
                ss += xv * xv;
            }
            ss = block_sum(ss, sred);
            float inv = rsqrtf(ss * (1.f / D) + 1e-5f);
            const float* l1 = ln1 + l * D;
            const float* mk = tmk + l * D;
            const float* mv = tmv + l * D;
            const float* mr = tmr + l * D;
            for (int j = tid; j < D; j += NT) {
                float xv  = sbuf[3 * D + j];
                float xxj = xv * inv * l1[j];
                float sa  = st_l[D + j];
                float a_ = mk[j]; sbuf[j]         = xxj * a_ + sa * (1.f - a_);
                float b_ = mv[j]; sbuf[D + j]     = xxj * b_ + sa * (1.f - b_);
                float c_ = mr[j]; sbuf[2 * D + j] = xxj * c_ + sa * (1.f - c_);
                if (bid == 0) ost_l[D + j] = xxj;   // new sa_x
            }
            __syncthreads();
            // publish folded x into the other buffer (blocks 0,1 cover D once)
            if (bid < 2) g_x[np][bid * NT + tid] = sbuf[3 * D + bid * NT + tid];
            dual_items(3 * D, gw, nwG, lane,
                [&](int t) {
                    int m = t >> 10, r = t & 1023;
                    const float* base = (m == 0) ? kwl : ((m == 1) ? vwl : rwl);
                    return base + (size_t)r * D;
                },
                [&](int t) { return (const float*)(sbuf + (t >> 10) * 1024); },
                [&](int t, float r) {
                    if (lane == 0) {
                        int m = t >> 10, rr = t & 1023;
                        if (m == 0)      g_k[rr] = r;
                        else if (m == 1) g_v[rr] = r;
                        else             g_r[rr] = r;
                    }
                });
        }
        grid_barrier(nb);

        // ---------- stage B: WKV elementwise; ow matvec into g_x[np] ----------
        {
            const float* tfl = tfirst + l * D;
            const float* tdl = tdecay + l * D;
            for (int j = tid; j < D; j += NT) {
                float k  = g_k[j], v = g_v[j], rr = g_r[j];
                float aa = st_l[2 * D + j], bb = st_l[3 * D + j], pp = st_l[4 * D + j];
                float ww = tfl[j] + k;
                float pm = fmaxf(pp, ww);
                float e1 = __expf(pp - pm), e2 = __expf(ww - pm);
                float a  = e1 * aa + e2 * v;
                float b  = e1 * bb + e2;
                float sr = 1.f / (1.f + __expf(-rr));
                sbuf[j] = sr * (a / b);
                if (bid == 0) {
                    float ww2 = pp + tdl[j];
                    float p2  = fmaxf(ww2, k);
                    float e1b = __expf(ww2 - p2), e2b = __expf(k - p2);
                    ost_l[2 * D + j] = e1b * aa + e2b * v;   // naa
                    ost_l[3 * D + j] = e1b * bb + e2b;       // nbb
                    ost_l[4 * D + j] = p2;                   // pp
                }
            }
            __syncthreads();
            for (int t = gw; t < D; t += nwG) {
                float dv = dot1k(owl + (size_t)t * D, sbuf, lane);
                if (lane == 0) g_x[np][t] += dv;
            }
        }
        grid_barrier(nb);

        // ---------- stage C: rms2 + channel-mix prep; fkw/frw ----------
        {
            float ss = 0.f;
            for (int j = tid; j < D; j += NT) { float t = g_x[np][j]; ss += t * t; }
            ss = block_sum(ss, sred);
            float inv = rsqrtf(ss * (1.f / D) + 1e-5f);
            const float* l2l = ln2  + l * D;
            const float* fmk = ftmk + l * D;
            const float* fmr = ftmr + l * D;
            for (int j = tid; j < D; j += NT) {
                float yyj = g_x[np][j] * inv * l2l[j];
                float ff  = st_l[j];
                float a_ = fmk[j]; sbuf[j]     = yyj * a_ + ff * (1.f - a_);
                float b_ = fmr[j]; sbuf[D + j] = yyj * b_ + ff * (1.f - b_);
                if (bid == 0) ost_l[j] = yyj;   // new ff_x
            }
            // zero accD for this layer's stage D (blocks 2,3 cover D once)
            if (bid >= 2 && bid < 4) g_accD[(bid - 2) * NT + tid] = 0.f;
            __syncthreads();
            dual_items(HD + D, gw, nwG, lane,
                [&](int t) {
                    return (t < HD) ? fkwl + (size_t)t * D
                                    : frwl + (size_t)(t - HD) * D;
                },
                [&](int t) { return (const float*)((t < HD) ? sbuf : sbuf + D); },
                [&](int t, float r) {
                    if (lane == 0) {
                        if (t < HD) { r = fmaxf(r, 0.f); g_k2[t] = r * r; }
                        else        g_r2[t - HD] = r;
                    }
                });
        }
        grid_barrier(nb);

        // ---------- stage D: fvw 1K-chunk tasks into accD ----------
        {
            for (int j = tid; j < HD; j += NT) sbuf[j] = g_k2[j];
            __syncthreads();
            dual_items(4 * D, gw, nwG, lane,
                [&](int t) { return fvwl + (size_t)(t >> 2) * HD + (t & 3) * 1024; },
                [&](int t) { return (const float*)(sbuf + (t & 3) * 1024); },
                [&](int t, float r) {
                    if (lane == 0) atomicAdd(&g_accD[t >> 2], r);
                });
        }
        grid_barrier(nb);
    }

    // ---------- head: fold layer-11 tail, rms, logits ----------
    {
        const int pf = LNUM & 1;           // = 0: entry buffer after layer 11
        const float scp = (LNUM % 6 == 0) ? 0.5f : 1.0f;
        float ss = 0.f;
        for (int j = tid; j < D; j += NT) {
            float sr = 1.f / (1.f + __expf(-g_r2[j]));
            float xv = (g_x[pf][j] + sr * g_accD[j]) * scp;
            sbuf[D + j] = xv;
            ss += xv * xv;
        }
        ss = block_sum(ss, sred);
        float inv = rsqrtf(ss * (1.f / D) + 1e-5f);
        for (int j = tid; j < D; j += NT) sbuf[j] = sbuf[D + j] * inv * lnout[j];
        __syncthreads();
        dual_items(VOCAB, gw, nwG, lane,
            [&](int t) { return head + (size_t)t * D; },
            [&](int t) { (void)t; return (const float*)sbuf; },
            [&](int t, float r) { if (lane == 0) out_logits[t] = r; });
    }
}

extern "C" void kernel_launch(void* const* d_in, const int* in_sizes, int n_in,
                              void* d_out, int out_size) {
    (void)in_sizes; (void)n_in; (void)out_size;
    int nb = 0;
    cudaDeviceGetAttribute(&nb, cudaDevAttrMultiProcessorCount, 0);
    if (nb <= 0) nb = 148;
    if (nb > 1024) nb = 1024;

    rwkv_persistent<<<nb, NT>>>(
        (const int*)  d_in[0],   // ctx
        (const float*)d_in[1],   // state
        (const float*)d_in[2],   // emb
        (const float*)d_in[3],   // ln0_w
        (const float*)d_in[4],   // ln1_w
        (const float*)d_in[5],   // ln2_w
        (const float*)d_in[6],   // lnout_w
        (const float*)d_in[7],   // att_tmk
        (const float*)d_in[8],   // att_tmv
        (const float*)d_in[9],   // att_tmr
        (const float*)d_in[10],  // att_tfirst
        (const float*)d_in[11],  // att_tdecay
        (const float*)d_in[12],  // att_kw
        (const float*)d_in[13],  // att_vw
        (const float*)d_in[14],  // att_rw
        (const float*)d_in[15],  // att_ow
        (const float*)d_in[16],  // ffn_tmk
        (const float*)d_in[17],  // ffn_tmr
        (const float*)d_in[18],  // ffn_kw
        (const float*)d_in[19],  // ffn_vw
        (const float*)d_in[20],  // ffn_rw
        (const float*)d_in[21],  // head
        (float*)d_out, nb);
}

// round 12
// speedup vs baseline: 1.2636x; 1.0048x over previous
#include <cuda_runtime.h>

#define D     1024
#define HD    4096
#define LNUM  12
#define VOCAB 50257

// ---------------- global scratch ----------------
__device__ float g_x[D];
__device__ float g_k[D];
__device__ float g_v[D];
__device__ float g_r[D];
__device__ float g_k2[HD];
__device__ float g_r2[D];

// ---------------- block sum over 8 warps (256 threads) ----------------
__device__ __forceinline__ float bsum256(float v, float* sred) {
    int lane = threadIdx.x & 31, wid = threadIdx.x >> 5;
    #pragma unroll
    for (int o = 16; o; o >>= 1) v += __shfl_xor_sync(0xffffffffu, v, o);
    if (lane == 0) sred[wid] = v;
    __syncthreads();
    float t = 0.f;
    if (wid == 0) {
        t = (lane < 8) ? sred[lane] : 0.f;
        #pragma unroll
        for (int o = 4; o; o >>= 1) t += __shfl_xor_sync(0xffffffffu, t, o);
        if (lane == 0) sred[0] = t;
    }
    __syncthreads();
    float r = sred[0];
    __syncthreads();
    return r;
}

// ---------------- warp dot: 1024 floats (weights global, vec shared) ----------------
__device__ __forceinline__ float dot1k(const float* __restrict__ w,
                                       const float* __restrict__ vec, int lane) {
    const float4* __restrict__ w4 = reinterpret_cast<const float4*>(w);
    const float4* __restrict__ v4 = reinterpret_cast<const float4*>(vec);
    float4 a[8];
    #pragma unroll
    for (int u = 0; u < 8; u++) a[u] = __ldg(w4 + u * 32 + lane);
    float s0 = 0.f, s1 = 0.f, s2 = 0.f, s3 = 0.f;
    #pragma unroll
    for (int u = 0; u < 8; u++) {
        float4 b = v4[u * 32 + lane];
        s0 = fmaf(a[u].x, b.x, s0); s1 = fmaf(a[u].y, b.y, s1);
        s2 = fmaf(a[u].z, b.z, s2); s3 = fmaf(a[u].w, b.w, s3);
    }
    float t = (s0 + s1) + (s2 + s3);
    #pragma unroll
    for (int o = 16; o; o >>= 1) t += __shfl_xor_sync(0xffffffffu, t, o);
    return t;
}

// ---------------- warp dot: 512-float segment, both operands global ----------------
__device__ __forceinline__ float dot512g(const float* __restrict__ w,
                                         const float* __restrict__ v, int lane) {
    const float4* __restrict__ w4 = reinterpret_cast<const float4*>(w);
    const float4* __restrict__ v4 = reinterpret_cast<const float4*>(v);
    float4 a[4];
    #pragma unroll
    for (int u = 0; u < 4; u++) a[u] = __ldg(w4 + u * 32 + lane);
    float s0 = 0.f, s1 = 0.f, s2 = 0.f, s3 = 0.f;
    #pragma unroll
    for (int u = 0; u < 4; u++) {
        float4 b = __ldg(v4 + u * 32 + lane);
        s0 = fmaf(a[u].x, b.x, s0); s1 = fmaf(a[u].y, b.y, s1);
        s2 = fmaf(a[u].z, b.z, s2); s3 = fmaf(a[u].w, b.w, s3);
    }
    float t = (s0 + s1) + (s2 + s3);
    #pragma unroll
    for (int o = 16; o; o >>= 1) t += __shfl_xor_sync(0xffffffffu, t, o);
    return t;
}

// ================= K_emb: x = rms(emb[ctx], ln0) =================
__global__ void k_emb(const int* __restrict__ ctx, const float* __restrict__ emb,
                      const float* __restrict__ ln0) {
    __shared__ float sred[8];
    int tid = threadIdx.x;
    const float* e = emb + (size_t)ctx[0] * D;
    float ss = 0.f;
    for (int j = tid; j < D; j += 256) { float t = e[j]; ss += t * t; }
    ss = bsum256(ss, sred);
    float inv = rsqrtf(ss * (1.f / D) + 1e-5f);
    for (int j = tid; j < D; j += 256) g_x[j] = e[j] * inv * ln0[j];
}

// ================= K_A: rms + token-mix (redundant per block); k/v/r matvecs =================
// grid = 384 blocks x 256 thr; block b -> rows b*8..b*8+7 of [kw;vw;rw]
__global__ void k_sa_kvr(
    const float* __restrict__ ln1l, const float* __restrict__ mkl,
    const float* __restrict__ mvl,  const float* __restrict__ mrl,
    const float* __restrict__ sal,  float* __restrict__ ost_sax,
    const float* __restrict__ kwl,  const float* __restrict__ vwl,
    const float* __restrict__ rwl)
{
    __shared__ float vec[3 * D];
    __shared__ float sred[8];
    int tid = threadIdx.x, lane = tid & 31, w = tid >> 5;
    float ss = 0.f;
    for (int j = tid; j < D; j += 256) { float t = g_x[j]; ss += t * t; }
    ss = bsum256(ss, sred);
    float inv = rsqrtf(ss * (1.f / D) + 1e-5f);
    for (int j = tid; j < D; j += 256) {
        float xx = g_x[j] * inv * ln1l[j];
        float sa = sal[j];
        float a_ = mkl[j]; vec[j]         = xx * a_ + sa * (1.f - a_);
        float b_ = mvl[j]; vec[D + j]     = xx * b_ + sa * (1.f - b_);
        float c_ = mrl[j]; vec[2 * D + j] = xx * c_ + sa * (1.f - c_);
        if (blockIdx.x == 0) ost_sax[j] = xx;
    }
    __syncthreads();
    int t = blockIdx.x * 8 + w;          // 0..3071
    int m = t >> 10, r = t & 1023;
    const float* base = (m == 0) ? kwl : ((m == 1) ? vwl : rwl);
    float acc = dot1k(base + (size_t)r * D, vec + m * D, lane);
    if (lane == 0) {
        if (m == 0)      g_k[r] = acc;
        else if (m == 1) g_v[r] = acc;
        else             g_r[r] = acc;
    }
}

// ================= K_B: WKV prep (redundant); ow matvec; state writes =================
// grid = 128 blocks x 256 thr; block b -> rows b*8..b*8+7 of ow
__global__ void k_sa_out(
    const float* __restrict__ tfl, const float* __restrict__ tdl,
    const float* __restrict__ aal, const float* __restrict__ bbl,
    const float* __restrict__ ppl, float* __restrict__ ost_wkv,  // naa at +0, nbb at +D, pp at +2D
    const float* __restrict__ owl)
{
    __shared__ float vec[D];
    int tid = threadIdx.x, lane = tid & 31, w = tid >> 5;
    for (int j = tid; j < D; j += 256) {
        float k  = g_k[j], v = g_v[j], rr = g_r[j];
        float aa = aal[j], bb = bbl[j], pp = ppl[j];
        float ww = tfl[j] + k;
        float p  = fmaxf(pp, ww);
        float e1 = __expf(pp - p), e2 = __expf(ww - p);
        float a  = e1 * aa + e2 * v;
        float b  = e1 * bb + e2;
        float sr = 1.f / (1.f + __expf(-rr));
        vec[j] = sr * (a / b);
        if (blockIdx.x == 0) {
            float ww2 = pp + tdl[j];
            float p2  = fmaxf(ww2, k);
            float e1b = __expf(ww2 - p2), e2b = __expf(k - p2);
            ost_wkv[j]         = e1b * aa + e2b * v;   // naa
            ost_wkv[D + j]     = e1b * bb + e2b;       // nbb
            ost_wkv[2 * D + j] = p2;                   // pp
        }
    }
    __syncthreads();
    int row = blockIdx.x * 8 + w;        // 0..1023
    float dv = dot1k(owl + (size_t)row * D, vec, lane);
    if (lane == 0) g_x[row] += dv;
}

// ================= K_C: rms2 + channel-mix (redundant); fkw/frw matvecs =================
// grid = 640 blocks x 256 thr; rows 0..4095 fkw, 4096..5119 frw
__global__ void k_ff_kr(
    const float* __restrict__ ln2l, const float* __restrict__ fmkl,
    const float* __restrict__ fmrl, const float* __restrict__ ffl,
    float* __restrict__ ost_ffx,
    const float* __restrict__ fkwl, const float* __restrict__ frwl)
{
    __shared__ float vec[2 * D];
    __shared__ float sred[8];
    int tid = threadIdx.x, lane = tid & 31, w = tid >> 5;
    float ss = 0.f;
    for (int j = tid; j < D; j += 256) { float t = g_x[j]; ss += t * t; }
    ss = bsum256(ss, sred);
    float inv = rsqrtf(ss * (1.f / D) + 1e-5f);
    for (int j = tid; j < D; j += 256) {
        float yy = g_x[j] * inv * ln2l[j];
        float ff = ffl[j];
        float a_ = fmkl[j]; vec[j]     = yy * a_ + ff * (1.f - a_);
        float b_ = fmrl[j]; vec[D + j] = yy * b_ + ff * (1.f - b_);
        if (blockIdx.x == 0) ost_ffx[j] = yy;
    }
    __syncthreads();
    int t = blockIdx.x * 8 + w;          // 0..5119
    if (t < HD) {
        float r = dot1k(fkwl + (size_t)t * D, vec, lane);
        if (lane == 0) { r = fmaxf(r, 0.f); g_k2[t] = r * r; }
    } else {
        float r = dot1k(frwl + (size_t)(t - HD) * D, vec + D, lane);
        if (lane == 0) g_r2[t - HD] = r;
    }
}

// ================= K_D: fvw matvec; x epilogue =================
// grid = 1024 blocks x 256 thr; block = one 16KB row, warp w -> segment w*512
__global__ void k_ff_out(const float* __restrict__ fvwl, float sc)
{
    __shared__ float sred[8];
    int tid = threadIdx.x, lane = tid & 31, w = tid >> 5;
    int row = blockIdx.x;
    const float* wr = fvwl + (size_t)row * HD + w * 512;
    float part = dot512g(wr, g_k2 + w * 512, lane);
    if (lane == 0) sred[w] = part;
    __syncthreads();
    if (tid == 0) {
        float acc = 0.f;
        #pragma unroll
        for (int q = 0; q < 8; q++) acc += sred[q];
        float sr = 1.f / (1.f + __expf(-g_r2[row]));
        g_x[row] = (g_x[row] + sr * acc) * sc;
    }
}

// ================= K_head: rms (redundant) + logits =================
// grid = ceil(VOCAB/8) x 256 thr
__global__ void k_head(const float* __restrict__ lnout,
                       const float* __restrict__ head,
                       float* __restrict__ out_logits)
{
    __shared__ float vec[D];
    __shared__ float sred[8];
    int tid = threadIdx.x, lane = tid & 31, w = tid >> 5;
    float ss = 0.f;
    for (int j = tid; j < D; j += 256) { float t = g_x[j]; ss += t * t; }
    ss = bsum256(ss, sred);
    float inv = rsqrtf(ss * (1.f / D) + 1e-5f);
    for (int j = tid; j < D; j += 256) vec[j] = g_x[j] * inv * lnout[j];
    __syncthreads();
    int row = blockIdx.x * 8 + w;
    if (row < VOCAB) {
        float r = dot1k(head + (size_t)row * D, vec, lane);
        if (lane == 0) out_logits[row] = r;
    }
}

extern "C" void kernel_launch(void* const* d_in, const int* in_sizes, int n_in,
                              void* d_out, int out_size) {
    (void)in_sizes; (void)n_in; (void)out_size;
    const int*   ctx    = (const int*)  d_in[0];
    const float* st     = (const float*)d_in[1];
    const float* emb    = (const float*)d_in[2];
    const float* ln0    = (const float*)d_in[3];
    const float* ln1    = (const float*)d_in[4];
    const float* ln2    = (const float*)d_in[5];
    const float* lnout  = (const float*)d_in[6];
    const float* tmk    = (const float*)d_in[7];
    const float* tmv    = (const float*)d_in[8];
    const float* tmr    = (const float*)d_in[9];
    const float* tfirst = (const float*)d_in[10];
    const float* tdecay = (const float*)d_in[11];
    const float* kw     = (const float*)d_in[12];
    const float* vw     = (const float*)d_in[13];
    const float* rw     = (const float*)d_in[14];
    const float* ow     = (const float*)d_in[15];
    const float* ftmk   = (const float*)d_in[16];
    const float* ftmr   = (const float*)d_in[17];
    const float* fkw    = (const float*)d_in[18];
    const float* fvw    = (const float*)d_in[19];
    const float* frw    = (const float*)d_in[20];
    const float* head   = (const float*)d_in[21];
    float* out          = (float*)d_out;
    float* out_logits   = out;
    float* out_state    = out + VOCAB;

    k_emb<<<1, 256>>>(ctx, emb, ln0);

    for (int l = 0; l < LNUM; l++) {
        const float* st_l  = st        + (size_t)l * 5 * D;
        float*       ost_l = out_state + (size_t)l * 5 * D;
        k_sa_kvr<<<384, 256>>>(
            ln1 + l * D, tmk + l * D, tmv + l * D, tmr + l * D,
            st_l + D, ost_l + D,
            kw + (size_t)l * D * D, vw + (size_t)l * D * D, rw + (size_t)l * D * D);
        k_sa_out<<<128, 256>>>(
            tfirst + l * D, tdecay + l * D,
            st_l + 2 * D, st_l + 3 * D, st_l + 4 * D,
            ost_l + 2 * D,
            ow + (size_t)l * D * D);
        k_ff_kr<<<640, 256>>>(
            ln2 + l * D, ftmk + l * D, ftmr + l * D, st_l, ost_l,
            fkw + (size_t)l * HD * D, frw + (size_t)l * D * D);
        float sc = ((l + 1) % 6 == 0) ? 0.5f : 1.0f;
        k_ff_out<<<1024, 256>>>(fvw + (size_t)l * D * HD, sc);
    }

    k_head<<<(VOCAB + 7) / 8, 256>>>(lnout, head, out_logits);
}